// round 3
// baseline (speedup 1.0000x reference)
#include <cuda_runtime.h>

#define T_LEN 2048
typedef unsigned long long u64;

// ---- MUFU helpers ----
__device__ __forceinline__ float ex2f(float x){ float y; asm("ex2.approx.f32 %0, %1;" : "=f"(y) : "f"(x)); return y; }
__device__ __forceinline__ float rcpf(float x){ float y; asm("rcp.approx.f32 %0, %1;" : "=f"(y) : "f"(x)); return y; }

// ---- packed f32x2 helpers (sm_100+) ----
__device__ __forceinline__ u64 pk(float lo, float hi){ u64 d; asm("mov.b64 %0, {%1, %2};" : "=l"(d) : "f"(lo), "f"(hi)); return d; }
__device__ __forceinline__ void unpk(u64 d, float& lo, float& hi){ asm("mov.b64 {%0, %1}, %2;" : "=f"(lo), "=f"(hi) : "l"(d)); }
__device__ __forceinline__ u64 fma2_(u64 a, u64 b, u64 c){ u64 d; asm("fma.rn.f32x2 %0, %1, %2, %3;" : "=l"(d) : "l"(a), "l"(b), "l"(c)); return d; }
__device__ __forceinline__ u64 mul2_(u64 a, u64 b){ u64 d; asm("mul.rn.f32x2 %0, %1, %2;" : "=l"(d) : "l"(a), "l"(b)); return d; }
__device__ __forceinline__ u64 add2_(u64 a, u64 b){ u64 d; asm("add.rn.f32x2 %0, %1, %2;" : "=l"(d) : "l"(a), "l"(b)); return d; }

// 8 lanes per batch element; lane j owns hidden unit j of both layers (gate
// rows {j, j+8, j+16, j+24}, packed (i,f)/(g,o) in the dot products only).
// Activation scales (-log2e sigmoid, +2log2e tanh) folded into weights/biases.
// Layers software-pipelined: iteration t computes L1(t) and L2(t-1).
// block=32 -> 1024 CTAs: near-perfect SM load balance (~7 CTAs/SM).
__global__ void __launch_bounds__(32) lstm2_fused_kernel(
    const float* __restrict__ x,
    const float* __restrict__ w_ih1, const float* __restrict__ w_hh1,
    const float* __restrict__ b_ih1, const float* __restrict__ b_hh1,
    const float* __restrict__ w_ih2, const float* __restrict__ w_hh2,
    const float* __restrict__ b_ih2, const float* __restrict__ b_hh2,
    const float* __restrict__ fc_w, const float* __restrict__ fc_b,
    float* __restrict__ out, int B)
{
    const int tid = blockIdx.x * blockDim.x + threadIdx.x;
    const int b   = tid >> 3;
    if (b >= B) return;
    const int j   = tid & 7;
    const unsigned FULL = 0xffffffffu;

    const float L2E = 1.4426950408889634f;
    const float NL  = -L2E;         // sigmoid rows: exp(-a) = 2^(NL*a)
    const float PL  = 2.0f * L2E;   // tanh rows:    exp(2a) = 2^(PL*a)

    const int gi = j, gf = j + 8, gg = j + 16, go = j + 24;

    // ---- fold scales into packed weights (one-time) ----
    u64 whIF1[8], whGO1[8], wxIF2[8], wxGO2[8], whIF2[8], whGO2[8];
    #pragma unroll
    for (int k = 0; k < 8; k++) {
        whIF1[k] = pk(NL * w_hh1[gi*8+k], NL * w_hh1[gf*8+k]);
        whGO1[k] = pk(PL * w_hh1[gg*8+k], NL * w_hh1[go*8+k]);
        wxIF2[k] = pk(NL * w_ih2[gi*8+k], NL * w_ih2[gf*8+k]);
        wxGO2[k] = pk(PL * w_ih2[gg*8+k], NL * w_ih2[go*8+k]);
        whIF2[k] = pk(NL * w_hh2[gi*8+k], NL * w_hh2[gf*8+k]);
        whGO2[k] = pk(PL * w_hh2[gg*8+k], NL * w_hh2[go*8+k]);
    }
    const u64 wx1IF = pk(NL * w_ih1[gi], NL * w_ih1[gf]);
    const u64 wx1GO = pk(PL * w_ih1[gg], NL * w_ih1[go]);
    const u64 bIF1  = pk(NL*(b_ih1[gi]+b_hh1[gi]), NL*(b_ih1[gf]+b_hh1[gf]));
    const u64 bGO1  = pk(PL*(b_ih1[gg]+b_hh1[gg]), NL*(b_ih1[go]+b_hh1[go]));
    const u64 bIF2  = pk(NL*(b_ih2[gi]+b_hh2[gi]), NL*(b_ih2[gf]+b_hh2[gf]));
    const u64 bGO2  = pk(PL*(b_ih2[gg]+b_hh2[gg]), NL*(b_ih2[go]+b_hh2[go]));

    // ---- state ----
    float c1, c2 = 0.0f;
    u64 H1[8], H2[8];

    const float* xb = x + (size_t)b * T_LEN;

    // ---- prologue: L1 step 0 (h1=c1=0) ----
    {
        const float x0 = __ldg(&xb[0]);
        float ai, af, ag, ao;
        unpk(fma2_(wx1IF, pk(x0, x0), bIF1), ai, af);
        unpk(fma2_(wx1GO, pk(x0, x0), bGO1), ag, ao);
        float di = 1.f + ex2f(ai), df = 1.f + ex2f(af);
        float dg = 1.f + ex2f(ag), dn = 1.f + ex2f(ao);
        float rIF = rcpf(di * df), rGO = rcpf(dg * dn);
        float I = rIF * df, sg = rGO * dn, O = rGO * dg;
        c1 = I * fmaf(-2.f, sg, 1.f);
        float h1j = O * fmaf(-2.f, rcpf(ex2f(PL * c1) + 1.f), 1.f);
        #pragma unroll
        for (int k = 0; k < 8; k++) {
            float v = __shfl_sync(FULL, h1j, k, 8);
            H1[k] = pk(v, v);
            H2[k] = pk(0.f, 0.f);
        }
    }

    float xt_next = __ldg(&xb[1]);

    // ---- main loop: iteration t does L1(t) and L2(t-1) concurrently ----
    #pragma unroll 1
    for (int t = 1; t < T_LEN; t++) {
        const float xt = xt_next;
        xt_next = __ldg(&xb[(t + 1) & (T_LEN - 1)]);   // wraps harmlessly
        const u64 XT = pk(xt, xt);

        // L1(t) pre-acts: b1 + wx1*x + wh1.H1  (two parallel 4-chains)
        u64 aIF0 = fma2_(wx1IF, XT, bIF1);
        u64 aGO0 = fma2_(wx1GO, XT, bGO1);
        #pragma unroll
        for (int k = 0; k < 4; k++) {
            aIF0 = fma2_(whIF1[k], H1[k], aIF0);
            aGO0 = fma2_(whGO1[k], H1[k], aGO0);
        }
        u64 aIF1 = mul2_(whIF1[4], H1[4]);
        u64 aGO1 = mul2_(whGO1[4], H1[4]);
        #pragma unroll
        for (int k = 5; k < 8; k++) {
            aIF1 = fma2_(whIF1[k], H1[k], aIF1);
            aGO1 = fma2_(whGO1[k], H1[k], aGO1);
        }
        const u64 aIF = add2_(aIF0, aIF1);
        const u64 aGO = add2_(aGO0, aGO1);

        // L2(t-1) pre-acts: b2 + wh2.H2 + wx2.H1  (two parallel 8-chains)
        u64 eIF0 = bIF2, eGO0 = bGO2;
        #pragma unroll
        for (int k = 0; k < 8; k++) {
            eIF0 = fma2_(whIF2[k], H2[k], eIF0);
            eGO0 = fma2_(whGO2[k], H2[k], eGO0);
        }
        u64 eIF1 = mul2_(wxIF2[0], H1[0]);
        u64 eGO1 = mul2_(wxGO2[0], H1[0]);
        #pragma unroll
        for (int k = 1; k < 8; k++) {
            eIF1 = fma2_(wxIF2[k], H1[k], eIF1);
            eGO1 = fma2_(wxGO2[k], H1[k], eGO1);
        }
        const u64 eIF = add2_(eIF0, eIF1);
        const u64 eGO = add2_(eGO0, eGO1);

        // ---- L1 activations (scalar; one shared rcp per gate pair) ----
        float a_i, a_f, a_g, a_o; unpk(aIF, a_i, a_f); unpk(aGO, a_g, a_o);
        const float d1i = 1.f + ex2f(a_i), d1f = 1.f + ex2f(a_f);
        const float d1g = 1.f + ex2f(a_g), d1o = 1.f + ex2f(a_o);
        const float r1IF = rcpf(d1i * d1f), r1GO = rcpf(d1g * d1o);
        const float I1 = r1IF * d1f, F1 = r1IF * d1i;
        const float s1 = r1GO * d1o, O1 = r1GO * d1g;
        c1 = fmaf(F1, c1, I1 * fmaf(-2.f, s1, 1.f));
        const float h1j = O1 * fmaf(-2.f, rcpf(ex2f(PL * c1) + 1.f), 1.f);

        // ---- L2 activations (independent chain) ----
        float e_i, e_f, e_g, e_o; unpk(eIF, e_i, e_f); unpk(eGO, e_g, e_o);
        const float d2i = 1.f + ex2f(e_i), d2f = 1.f + ex2f(e_f);
        const float d2g = 1.f + ex2f(e_g), d2o = 1.f + ex2f(e_o);
        const float r2IF = rcpf(d2i * d2f), r2GO = rcpf(d2g * d2o);
        const float I2 = r2IF * d2f, F2 = r2IF * d2i;
        const float s2 = r2GO * d2o, O2 = r2GO * d2g;
        c2 = fmaf(F2, c2, I2 * fmaf(-2.f, s2, 1.f));
        const float h2j = O2 * fmaf(-2.f, rcpf(ex2f(PL * c2) + 1.f), 1.f);

        // ---- broadcast h1_t, h2_{t-1} within the 8-lane group ----
        #pragma unroll
        for (int k = 0; k < 8; k++) {
            float v1 = __shfl_sync(FULL, h1j, k, 8);
            float v2 = __shfl_sync(FULL, h2j, k, 8);
            H1[k] = pk(v1, v1);
            H2[k] = pk(v2, v2);
        }
    }

    // ---- epilogue: L2(T-1) ----
    float h2j;
    {
        u64 eIF0 = bIF2, eGO0 = bGO2;
        #pragma unroll
        for (int k = 0; k < 8; k++) {
            eIF0 = fma2_(whIF2[k], H2[k], eIF0);
            eGO0 = fma2_(whGO2[k], H2[k], eGO0);
        }
        u64 eIF1 = mul2_(wxIF2[0], H1[0]);
        u64 eGO1 = mul2_(wxGO2[0], H1[0]);
        #pragma unroll
        for (int k = 1; k < 8; k++) {
            eIF1 = fma2_(wxIF2[k], H1[k], eIF1);
            eGO1 = fma2_(wxGO2[k], H1[k], eGO1);
        }
        float e_i, e_f, e_g, e_o;
        unpk(add2_(eIF0, eIF1), e_i, e_f);
        unpk(add2_(eGO0, eGO1), e_g, e_o);
        const float d2i = 1.f + ex2f(e_i), d2f = 1.f + ex2f(e_f);
        const float d2g = 1.f + ex2f(e_g), d2o = 1.f + ex2f(e_o);
        const float r2IF = rcpf(d2i * d2f), r2GO = rcpf(d2g * d2o);
        const float I2 = r2IF * d2f, F2 = r2IF * d2i;
        const float s2 = r2GO * d2o, O2 = r2GO * d2g;
        c2 = fmaf(F2, c2, I2 * fmaf(-2.f, s2, 1.f));
        h2j = O2 * fmaf(-2.f, rcpf(ex2f(PL * c2) + 1.f), 1.f);
    }

    // ---- fc on final h2 ----
    float h2f[8];
    #pragma unroll
    for (int k = 0; k < 8; k++) h2f[k] = __shfl_sync(FULL, h2j, k, 8);
    if (j < 4) {
        float acc = fc_b[j];
        #pragma unroll
        for (int k = 0; k < 8; k++) acc = fmaf(fc_w[j*8+k], h2f[k], acc);
        out[b*4 + j] = acc;
    }
}

extern "C" void kernel_launch(void* const* d_in, const int* in_sizes, int n_in,
                              void* d_out, int out_size)
{
    const float* x     = (const float*)d_in[0];
    const float* w_ih1 = (const float*)d_in[1];
    const float* w_hh1 = (const float*)d_in[2];
    const float* b_ih1 = (const float*)d_in[3];
    const float* b_hh1 = (const float*)d_in[4];
    const float* w_ih2 = (const float*)d_in[5];
    const float* w_hh2 = (const float*)d_in[6];
    const float* b_ih2 = (const float*)d_in[7];
    const float* b_hh2 = (const float*)d_in[8];
    const float* fc_w  = (const float*)d_in[9];
    const float* fc_b  = (const float*)d_in[10];
    float* out = (float*)d_out;

    const int B = in_sizes[0] / T_LEN;      // 4096
    const int threads = B * 8;              // 32768
    const int block = 32;                   // 4 batches/CTA -> 1024 CTAs, ~7/SM balanced
    const int grid = (threads + block - 1) / block;

    lstm2_fused_kernel<<<grid, block>>>(x, w_ih1, w_hh1, b_ih1, b_hh1,
                                        w_ih2, w_hh2, b_ih2, b_hh2,
                                        fc_w, fc_b, out, B);
}